// round 1
// baseline (speedup 1.0000x reference)
#include <cuda_runtime.h>
#include <cuda_bf16.h>

#define B 64
#define C 1024
#define HW 1024
#define CSPLIT 8
#define CCHUNK (C / CSPLIT)   // 128

// Scratch (no device allocs allowed): partial scores + attention weights.
__device__ float g_partial[B * CSPLIT * HW];   // 2 MB
__device__ float g_attn[B * HW];               // 256 KB

// ---------------------------------------------------------------------------
// Pass 1: partial scores.  grid = (B*CSPLIT), block = 256 threads.
// Thread t owns 4 spatial positions (float4 at hw = 4t). Loop over 128
// channels of this chunk; each iteration the block reads 4 KB contiguous
// (fully coalesced 128B per warp).
// ---------------------------------------------------------------------------
__global__ __launch_bounds__(256) void scores_kernel(
    const float* __restrict__ x, const float* __restrict__ w)
{
    const int b  = blockIdx.x / CSPLIT;
    const int cs = blockIdx.x % CSPLIT;
    const int t  = threadIdx.x;          // float4 index over HW
    const int c0 = cs * CCHUNK;

    const float4* xb = reinterpret_cast<const float4*>(
        x + ((size_t)b * C + c0) * HW) + t;

    float4 acc = make_float4(0.f, 0.f, 0.f, 0.f);
    #pragma unroll 8
    for (int c = 0; c < CCHUNK; ++c) {
        const float wc = __ldg(&w[c0 + c]);
        const float4 v = xb[c * (HW / 4)];
        acc.x += v.x * wc;
        acc.y += v.y * wc;
        acc.z += v.z * wc;
        acc.w += v.w * wc;
    }
    reinterpret_cast<float4*>(g_partial + ((size_t)b * CSPLIT + cs) * HW)[t] = acc;
}

// ---------------------------------------------------------------------------
// Pass 2: reduce partials + bias, softmax over HW per batch.
// grid = B, block = 256 (8 warps). Thread t owns 4 hw positions.
// ---------------------------------------------------------------------------
__global__ __launch_bounds__(256) void softmax_kernel(
    const float* __restrict__ bias_ptr)
{
    __shared__ float s_red[8];
    const int b = blockIdx.x;
    const int t = threadIdx.x;
    const int lane = t & 31;
    const int warp = t >> 5;

    const float bias = *bias_ptr;
    float4 s = make_float4(bias, bias, bias, bias);
    #pragma unroll
    for (int cs = 0; cs < CSPLIT; ++cs) {
        const float4 p = reinterpret_cast<const float4*>(
            g_partial + ((size_t)b * CSPLIT + cs) * HW)[t];
        s.x += p.x; s.y += p.y; s.z += p.z; s.w += p.w;
    }

    // block max
    float m = fmaxf(fmaxf(s.x, s.y), fmaxf(s.z, s.w));
    #pragma unroll
    for (int o = 16; o; o >>= 1) m = fmaxf(m, __shfl_xor_sync(~0u, m, o));
    if (lane == 0) s_red[warp] = m;
    __syncthreads();
    if (warp == 0) {
        float v = s_red[lane & 7];
        #pragma unroll
        for (int o = 4; o; o >>= 1) v = fmaxf(v, __shfl_xor_sync(~0u, v, o));
        if (lane == 0) s_red[0] = v;
    }
    __syncthreads();
    const float M = s_red[0];
    __syncthreads();

    float4 e;
    e.x = __expf(s.x - M);
    e.y = __expf(s.y - M);
    e.z = __expf(s.z - M);
    e.w = __expf(s.w - M);

    // block sum
    float sum = e.x + e.y + e.z + e.w;
    #pragma unroll
    for (int o = 16; o; o >>= 1) sum += __shfl_xor_sync(~0u, sum, o);
    if (lane == 0) s_red[warp] = sum;
    __syncthreads();
    if (warp == 0) {
        float v = s_red[lane & 7];
        #pragma unroll
        for (int o = 4; o; o >>= 1) v += __shfl_xor_sync(~0u, v, o);
        if (lane == 0) s_red[0] = v;
    }
    __syncthreads();
    const float Zinv = 1.0f / s_red[0];

    float4 a;
    a.x = e.x * Zinv; a.y = e.y * Zinv; a.z = e.z * Zinv; a.w = e.w * Zinv;
    reinterpret_cast<float4*>(g_attn + (size_t)b * HW)[t] = a;
}

// ---------------------------------------------------------------------------
// Pass 3: weighted spatial pooling. One warp per (b, c) row: dot of 1024
// contiguous floats with attn[b,:] (4 KB, L1/L2-resident per block).
// grid = B*C/8, block = 256 (8 warps -> 8 rows, same batch within a block
// since C=1024 is a multiple of 8).
// ---------------------------------------------------------------------------
__global__ __launch_bounds__(256) void pool_kernel(
    const float* __restrict__ x, float* __restrict__ out)
{
    const int row  = blockIdx.x * 8 + (threadIdx.x >> 5);  // b*C + c
    const int lane = threadIdx.x & 31;
    const int b    = row >> 10;                            // / C

    const float4* xr = reinterpret_cast<const float4*>(x + (size_t)row * HW);
    const float4* ar = reinterpret_cast<const float4*>(g_attn + (size_t)b * HW);

    float acc = 0.f;
    #pragma unroll
    for (int i = 0; i < 8; ++i) {
        const float4 v = xr[lane + i * 32];
        const float4 a = __ldg(&ar[lane + i * 32]);
        acc += v.x * a.x + v.y * a.y + v.z * a.z + v.w * a.w;
    }
    #pragma unroll
    for (int o = 16; o; o >>= 1) acc += __shfl_xor_sync(~0u, acc, o);
    if (lane == 0) out[row] = acc;
}

// ---------------------------------------------------------------------------
extern "C" void kernel_launch(void* const* d_in, const int* in_sizes, int n_in,
                              void* d_out, int out_size)
{
    const float* x      = (const float*)d_in[0];
    const float* attn_w = (const float*)d_in[1];
    const float* attn_b = (const float*)d_in[2];
    float* out          = (float*)d_out;

    scores_kernel<<<B * CSPLIT, 256>>>(x, attn_w);
    softmax_kernel<<<B, 256>>>(attn_b);
    pool_kernel<<<(B * C) / 8, 256>>>(x, out);
}